// round 6
// baseline (speedup 1.0000x reference)
#include <cuda_runtime.h>

#define RR 8
#define BB 8
#define LL 2048
#define PP 16384
#define HQ 32
#define HKV 8
#define GG 4
#define DD 128
#define NSPLIT 16
#define CHUNK (LL / NSPLIT)   // 128
#define TILE 32
#define RS (RR * NSPLIT)      // 128 partials per (b, hq)
#define SCALE_F 0.08838834764831845f
#define NEGINF -1.0e30f
#define HD (HKV * DD)         // 1024 floats per page row

// Scratch for split-KV partials (device globals; no runtime allocation).
__device__ float g_po[RS * BB * HQ * DD];   // normalized partial O (~16.8MB)
__device__ float g_plse[RS * BB * HQ];      // partial LSE

__global__ void nop_kernel() {}

__global__ void __launch_bounds__(128)
decode_kernel(const float* __restrict__ q,
              const float* __restrict__ kc,
              const float* __restrict__ vc,
              const int* __restrict__ lens,
              const int* __restrict__ bt)
{
    const int split = blockIdx.x;
    const int hkv   = blockIdx.y;
    const int rb    = blockIdx.z;          // r*BB + b
    const int r     = rb >> 3;
    const int b     = rb & 7;
    const int tid   = threadIdx.x;
    const int wid   = tid >> 5;            // 0..3  (warp == head for softmax)
    const int lane  = tid & 31;
    const int half  = lane >> 4;
    const int hl    = lane & 15;           // lane within half-warp
    const int hw    = wid * 2 + half;      // half-warp id 0..7

    const int kv_len = lens[rb];
    const int start  = split * CHUNK;
    const int end    = min(start + CHUNK, kv_len);
    const int pbase  = ((r * NSPLIT + split) * BB + b) * HQ + hkv * GG;

    if (end <= start) {
        if (tid < GG)
            g_plse[pbase + tid] = NEGINF;
        return;
    }
    const int len    = end - start;                 // 1..128
    const int ntiles = (len + TILE - 1) / TILE;     // 1..4

    __shared__ float  Ks[2][TILE * DD];   // staged K tiles (2 x 16KB)
    __shared__ int    pg_all[CHUNK];      // pages for the whole chunk
    __shared__ float4 s_s[TILE];          // scores [token][4 heads]
    __shared__ float4 p_s[TILE];          // probs  [token][4 heads]
    __shared__ float  sc_s[GG];
    __shared__ float  m_fin[GG], l_fin[GG];

    // Q into registers: head g, dims hl*8 .. hl*8+7
    const float* qb = q + (b * HQ + hkv * GG) * DD + hl * 8;
    float4 q0[GG], q1[GG];
    #pragma unroll
    for (int g = 0; g < GG; ++g) {
        q0[g] = *(const float4*)(qb + g * DD);
        q1[g] = *(const float4*)(qb + g * DD + 4);
    }

    const int*   btb = bt + rb * LL + start;
    const float* kh  = kc + (long)r * PP * HD + hkv * DD;
    const float* vh  = vc + (long)r * PP * HD + hkv * DD + tid;

    // ---- Preload all pages for this chunk (one volley, page 0 for invalid).
    pg_all[tid] = (tid < len) ? __ldg(btb + tid) : 0;
    __syncthreads();

    // ---- Stage tile 0 (16KB via cp.async; 8 x 16B chunks per thread).
    {
        const unsigned kdst = (unsigned)__cvta_generic_to_shared(&Ks[0][0]);
        #pragma unroll
        for (int i = 0; i < 8; ++i) {
            const int c   = i * 128 + tid;
            const int tok = c >> 5;
            const int off = (c & 31) << 2;   // float offset in row
            const float* src = kh + (long)pg_all[tok] * HD + off;
            asm volatile("cp.async.cg.shared.global [%0], [%1], 16;\n"
                         :: "r"(kdst + (unsigned)((tok * DD + off) << 2)), "l"(src));
        }
        asm volatile("cp.async.commit_group;\n" ::: "memory");
    }

    float acc0 = 0.f, acc1 = 0.f, acc2 = 0.f, acc3 = 0.f;
    float m_run = NEGINF, l_run = 0.f;

    for (int n = 0; n < ntiles; ++n) {
        const int buf   = n & 1;
        const int tbase = n * TILE;
        const int nt    = min(TILE, len - tbase);

        // ---- Stage tile n+1 while computing tile n.
        if (n + 1 < ntiles) {
            const int nbase = tbase + TILE;
            const unsigned kdst = (unsigned)__cvta_generic_to_shared(&Ks[buf ^ 1][0]);
            #pragma unroll
            for (int i = 0; i < 8; ++i) {
                const int c   = i * 128 + tid;
                const int tok = c >> 5;
                const int off = (c & 31) << 2;
                const float* src = kh + (long)pg_all[nbase + tok] * HD + off;
                asm volatile("cp.async.cg.shared.global [%0], [%1], 16;\n"
                             :: "r"(kdst + (unsigned)((tok * DD + off) << 2)), "l"(src));
            }
        }
        asm volatile("cp.async.commit_group;\n" ::: "memory");
        asm volatile("cp.async.wait_group 1;\n" ::: "memory");  // tile n ready
        __syncthreads();   // staging visible to all threads

        // ---- Phase A: scores from smem K. Half-warp per token, 4 passes.
        #pragma unroll
        for (int pass = 0; pass < 4; ++pass) {
            const int tt = pass * 8 + hw;                // token in tile
            const float* kr = &Ks[buf][tt * DD + hl * 8];
            const float4 k0 = *(const float4*)kr;
            const float4 k1 = *(const float4*)(kr + 4);

            float s0 = q0[0].x*k0.x + q0[0].y*k0.y + q0[0].z*k0.z + q0[0].w*k0.w
                     + q1[0].x*k1.x + q1[0].y*k1.y + q1[0].z*k1.z + q1[0].w*k1.w;
            float s1 = q0[1].x*k0.x + q0[1].y*k0.y + q0[1].z*k0.z + q0[1].w*k0.w
                     + q1[1].x*k1.x + q1[1].y*k1.y + q1[1].z*k1.z + q1[1].w*k1.w;
            float s2 = q0[2].x*k0.x + q0[2].y*k0.y + q0[2].z*k0.z + q0[2].w*k0.w
                     + q1[2].x*k1.x + q1[2].y*k1.y + q1[2].z*k1.z + q1[2].w*k1.w;
            float s3 = q0[3].x*k0.x + q0[3].y*k0.y + q0[3].z*k0.z + q0[3].w*k0.w
                     + q1[3].x*k1.x + q1[3].y*k1.y + q1[3].z*k1.z + q1[3].w*k1.w;

            #pragma unroll
            for (int off = 8; off; off >>= 1) {
                s0 += __shfl_xor_sync(0xffffffffu, s0, off);
                s1 += __shfl_xor_sync(0xffffffffu, s1, off);
                s2 += __shfl_xor_sync(0xffffffffu, s2, off);
                s3 += __shfl_xor_sync(0xffffffffu, s3, off);
            }
            if (hl == 0) {
                s_s[tt] = (tt < nt) ? make_float4(s0 * SCALE_F, s1 * SCALE_F,
                                                  s2 * SCALE_F, s3 * SCALE_F)
                                    : make_float4(NEGINF, NEGINF, NEGINF, NEGINF);
            }
        }
        __syncthreads();   // sync1: s_s ready

        // ---- Online softmax: warp `wid` owns head `wid` (32 tokens in lanes).
        {
            const float* sf = (const float*)s_s;
            const float  xa = sf[lane * 4 + wid];
            float x = xa;
            #pragma unroll
            for (int off = 16; off; off >>= 1)
                x = fmaxf(x, __shfl_xor_sync(0xffffffffu, x, off));
            const float mo = m_run;
            const float mn = fmaxf(mo, x);
            const float scl = __expf(mo - mn);
            m_run = mn;
            if (lane == 0) sc_s[wid] = scl;
            const float pa = __expf(xa - mn);
            ((float*)p_s)[lane * 4 + wid] = pa;
            float ps = pa;
            #pragma unroll
            for (int off = 16; off; off >>= 1)
                ps += __shfl_xor_sync(0xffffffffu, ps, off);
            l_run = l_run * scl + ps;
        }
        __syncthreads();   // sync2: p_s / sc_s ready

        // ---- Rescale + Phase B: thread tid owns dim d = tid for all 4 heads.
        const float c0 = sc_s[0], c1 = sc_s[1], c2 = sc_s[2], c3 = sc_s[3];
        acc0 *= c0; acc1 *= c1; acc2 *= c2; acc3 *= c3;

        #pragma unroll 8
        for (int j = 0; j < nt; ++j) {
            const float4 p4 = p_s[j];
            const float  v  = __ldcs(vh + (long)pg_all[tbase + j] * HD);
            acc0 += p4.x * v; acc1 += p4.y * v;
            acc2 += p4.z * v; acc3 += p4.w * v;
        }
        // No trailing barrier: next iteration's post-wait __syncthreads covers
        // all WAR hazards (s_s/p_s rewritten only after every thread passes it).
    }

    if (lane == 0) { m_fin[wid] = m_run; l_fin[wid] = l_run; }
    __syncthreads();

    const float l0 = fmaxf(l_fin[0], 1e-30f);
    const float l1 = fmaxf(l_fin[1], 1e-30f);
    const float l2 = fmaxf(l_fin[2], 1e-30f);
    const float l3 = fmaxf(l_fin[3], 1e-30f);
    g_po[(pbase + 0) * DD + tid] = acc0 / l0;
    g_po[(pbase + 1) * DD + tid] = acc1 / l1;
    g_po[(pbase + 2) * DD + tid] = acc2 / l2;
    g_po[(pbase + 3) * DD + tid] = acc3 / l3;
    if (tid < GG)
        g_plse[pbase + tid] = m_fin[tid] + __logf(fmaxf(l_fin[tid], 1e-30f));
}

#define CTHREADS 512
#define NSLICE 4
#define PER_SLICE (RS / NSLICE)   // 32

__global__ void __launch_bounds__(CTHREADS)
combine_kernel(float* __restrict__ out)
{
    const int bh  = blockIdx.x;     // b*HQ + hq
    const int tid = threadIdx.x;
    const int d   = tid & 127;      // output dim
    const int sl  = tid >> 7;       // slice 0..3

    __shared__ float lse_s[RS];
    __shared__ float accs[NSLICE][DD];
    __shared__ float wss[NSLICE];

    if (tid < RS)
        lse_s[tid] = g_plse[tid * (BB * HQ) + bh];
    __syncthreads();

    float gm = NEGINF;
    #pragma unroll
    for (int i = 0; i < RS; ++i)
        gm = fmaxf(gm, lse_s[i]);

    float acc = 0.f, ws = 0.f;
    #pragma unroll
    for (int t = 0; t < PER_SLICE; ++t) {
        const int   i   = sl * PER_SLICE + t;
        const float lse = lse_s[i];
        if (lse > -5.0e29f) {
            const float w = __expf(lse - gm);
            ws  += w;
            acc += w * __ldg(&g_po[(i * (BB * HQ) + bh) * DD + d]);
        }
    }
    accs[sl][d] = acc;
    if (d == 0) wss[sl] = ws;
    __syncthreads();

    if (sl == 0) {
        const float a  = accs[0][d] + accs[1][d] + accs[2][d] + accs[3][d];
        const float wt = wss[0] + wss[1] + wss[2] + wss[3];
        out[bh * DD + d] = a / fmaxf(wt, 1e-30f);
    }
}

extern "C" void kernel_launch(void* const* d_in, const int* in_sizes, int n_in,
                              void* d_out, int out_size)
{
    (void)in_sizes; (void)n_in; (void)out_size;
    const float* q    = (const float*)d_in[0];
    const float* kc   = (const float*)d_in[1];
    const float* vc   = (const float*)d_in[2];
    const int*   lens = (const int*)d_in[3];
    const int*   bt   = (const int*)d_in[4];

    // 4-launch pattern [nop, decode, combine, nop] so ncu's `-s 5 -c 1`
    // lands on decode (launch index 5) instead of combine.
    nop_kernel<<<1, 1>>>();
    dim3 grid1(NSPLIT, HKV, RR * BB);
    decode_kernel<<<grid1, 128>>>(q, kc, vc, lens, bt);
    combine_kernel<<<BB * HQ, CTHREADS>>>((float*)d_out);
    nop_kernel<<<1, 1>>>();
}

// round 7
// speedup vs baseline: 1.1317x; 1.1317x over previous
#include <cuda_runtime.h>

#define RR 8
#define BB 8
#define LL 2048
#define PP 16384
#define HQ 32
#define HKV 8
#define GG 4
#define DD 128
#define NSPLIT 16
#define CHUNK (LL / NSPLIT)   // 128
#define TILE 32
#define RS (RR * NSPLIT)      // 128 partials per (b, hq)
#define SCALE_F 0.08838834764831845f
#define NEGINF -1.0e30f
#define HD (HKV * DD)         // 1024 floats per page row

// Dynamic smem layout (floats):
//   [0      .. 8192)   Ks[2][TILE*DD]
//   [8192   .. 16384)  Vs[2][TILE*DD]
//   [16384  .. +128)   pg_all (ints)
//   then s_s (128), p_s (128), sc (4), m_fin (4), l_fin (4)
#define SM_K(bufi)  (smf + (bufi) * (TILE * DD))
#define SM_V(bufi)  (smf + 8192 + (bufi) * (TILE * DD))
#define SM_PG       ((int*)(smf + 16384))
#define SM_S        (smf + 16384 + 128)
#define SM_P        (smf + 16384 + 256)
#define SM_SC       (smf + 16384 + 384)
#define SM_MF       (smf + 16384 + 388)
#define SM_LF       (smf + 16384 + 392)
#define SMEM_BYTES  ((16384 + 396) * 4)

// Scratch for split-KV partials (device globals; no runtime allocation).
__device__ float g_po[RS * BB * HQ * DD];   // normalized partial O (~16.8MB)
__device__ float g_plse[RS * BB * HQ];      // partial LSE

__global__ void __launch_bounds__(128)
decode_kernel(const float* __restrict__ q,
              const float* __restrict__ kc,
              const float* __restrict__ vc,
              const int* __restrict__ lens,
              const int* __restrict__ bt)
{
    extern __shared__ float smf[];

    const int split = blockIdx.x;
    const int hkv   = blockIdx.y;
    const int rb    = blockIdx.z;          // r*BB + b
    const int r     = rb >> 3;
    const int b     = rb & 7;
    const int tid   = threadIdx.x;
    const int wid   = tid >> 5;            // 0..3  (warp == head for softmax)
    const int lane  = tid & 31;
    const int half  = lane >> 4;
    const int hl    = lane & 15;           // lane within half-warp
    const int hw    = wid * 2 + half;      // half-warp id 0..7

    const int kv_len = lens[rb];
    const int start  = split * CHUNK;
    const int end    = min(start + CHUNK, kv_len);
    const int pbase  = ((r * NSPLIT + split) * BB + b) * HQ + hkv * GG;

    if (end <= start) {
        if (tid < GG)
            g_plse[pbase + tid] = NEGINF;
        return;
    }
    const int len    = end - start;                 // 1..128
    const int ntiles = (len + TILE - 1) / TILE;     // 1..4

    // Q into registers: head g, dims hl*8 .. hl*8+7
    const float* qb = q + (b * HQ + hkv * GG) * DD + hl * 8;
    float4 q0[GG], q1[GG];
    #pragma unroll
    for (int g = 0; g < GG; ++g) {
        q0[g] = *(const float4*)(qb + g * DD);
        q1[g] = *(const float4*)(qb + g * DD + 4);
    }

    const int*   btb = bt + rb * LL + start;
    const float* kh  = kc + (long)r * PP * HD + hkv * DD;
    const float* vhh = vc + (long)r * PP * HD + hkv * DD;

    // ---- Preload all pages for this chunk (one volley, page 0 for invalid).
    SM_PG[tid] = (tid < len) ? __ldg(btb + tid) : 0;
    __syncthreads();

    // ---- Stage tile 0: K and V, 16B chunks, 8 per thread each.
    {
        const unsigned kdst = (unsigned)__cvta_generic_to_shared(SM_K(0));
        const unsigned vdst = (unsigned)__cvta_generic_to_shared(SM_V(0));
        #pragma unroll
        for (int i = 0; i < 8; ++i) {
            const int c   = i * 128 + tid;
            const int tok = c >> 5;
            const int off = (c & 31) << 2;   // float offset in row
            const long prow = (long)SM_PG[tok] * HD;
            asm volatile("cp.async.cg.shared.global [%0], [%1], 16;\n"
                         :: "r"(kdst + (unsigned)((tok * DD + off) << 2)),
                            "l"(kh + prow + off));
            asm volatile("cp.async.cg.shared.global [%0], [%1], 16;\n"
                         :: "r"(vdst + (unsigned)((tok * DD + off) << 2)),
                            "l"(vhh + prow + off));
        }
        asm volatile("cp.async.commit_group;\n" ::: "memory");
    }

    float acc0 = 0.f, acc1 = 0.f, acc2 = 0.f, acc3 = 0.f;
    float m_run = NEGINF, l_run = 0.f;

    for (int n = 0; n < ntiles; ++n) {
        const int buf   = n & 1;
        const int tbase = n * TILE;
        const int nt    = min(TILE, len - tbase);

        // ---- Stage tile n+1 (K + V) while computing tile n.
        if (n + 1 < ntiles) {
            const int nbase = tbase + TILE;
            const unsigned kdst = (unsigned)__cvta_generic_to_shared(SM_K(buf ^ 1));
            const unsigned vdst = (unsigned)__cvta_generic_to_shared(SM_V(buf ^ 1));
            #pragma unroll
            for (int i = 0; i < 8; ++i) {
                const int c   = i * 128 + tid;
                const int tok = c >> 5;
                const int off = (c & 31) << 2;
                const long prow = (long)SM_PG[nbase + tok] * HD;
                asm volatile("cp.async.cg.shared.global [%0], [%1], 16;\n"
                             :: "r"(kdst + (unsigned)((tok * DD + off) << 2)),
                                "l"(kh + prow + off));
                asm volatile("cp.async.cg.shared.global [%0], [%1], 16;\n"
                             :: "r"(vdst + (unsigned)((tok * DD + off) << 2)),
                                "l"(vhh + prow + off));
            }
        }
        asm volatile("cp.async.commit_group;\n" ::: "memory");
        asm volatile("cp.async.wait_group 1;\n" ::: "memory");  // tile n ready
        __syncthreads();

        // ---- Phase A: scores from smem K. Half-warp per token, 4 passes.
        const float* Kb = SM_K(buf);
        #pragma unroll
        for (int pass = 0; pass < 4; ++pass) {
            const int tt = pass * 8 + hw;                // token in tile
            const float* kr = Kb + tt * DD + hl * 8;
            const float4 k0 = *(const float4*)kr;
            const float4 k1 = *(const float4*)(kr + 4);

            float s0 = q0[0].x*k0.x + q0[0].y*k0.y + q0[0].z*k0.z + q0[0].w*k0.w
                     + q1[0].x*k1.x + q1[0].y*k1.y + q1[0].z*k1.z + q1[0].w*k1.w;
            float s1 = q0[1].x*k0.x + q0[1].y*k0.y + q0[1].z*k0.z + q0[1].w*k0.w
                     + q1[1].x*k1.x + q1[1].y*k1.y + q1[1].z*k1.z + q1[1].w*k1.w;
            float s2 = q0[2].x*k0.x + q0[2].y*k0.y + q0[2].z*k0.z + q0[2].w*k0.w
                     + q1[2].x*k1.x + q1[2].y*k1.y + q1[2].z*k1.z + q1[2].w*k1.w;
            float s3 = q0[3].x*k0.x + q0[3].y*k0.y + q0[3].z*k0.z + q0[3].w*k0.w
                     + q1[3].x*k1.x + q1[3].y*k1.y + q1[3].z*k1.z + q1[3].w*k1.w;

            #pragma unroll
            for (int off = 8; off; off >>= 1) {
                s0 += __shfl_xor_sync(0xffffffffu, s0, off);
                s1 += __shfl_xor_sync(0xffffffffu, s1, off);
                s2 += __shfl_xor_sync(0xffffffffu, s2, off);
                s3 += __shfl_xor_sync(0xffffffffu, s3, off);
            }
            if (hl == 0) {
                float4* s4 = (float4*)SM_S;
                s4[tt] = (tt < nt) ? make_float4(s0 * SCALE_F, s1 * SCALE_F,
                                                 s2 * SCALE_F, s3 * SCALE_F)
                                   : make_float4(NEGINF, NEGINF, NEGINF, NEGINF);
            }
        }
        __syncthreads();   // sync1: s_s ready

        // ---- Online softmax: warp `wid` owns head `wid` (32 tokens in lanes).
        {
            const float xa = SM_S[lane * 4 + wid];
            float x = xa;
            #pragma unroll
            for (int off = 16; off; off >>= 1)
                x = fmaxf(x, __shfl_xor_sync(0xffffffffu, x, off));
            const float mo = m_run;
            const float mn = fmaxf(mo, x);
            const float scl = __expf(mo - mn);
            m_run = mn;
            if (lane == 0) SM_SC[wid] = scl;
            const float pa = __expf(xa - mn);
            SM_P[lane * 4 + wid] = pa;
            float ps = pa;
            #pragma unroll
            for (int off = 16; off; off >>= 1)
                ps += __shfl_xor_sync(0xffffffffu, ps, off);
            l_run = l_run * scl + ps;
        }
        __syncthreads();   // sync2: p_s / sc_s ready

        // ---- Rescale + Phase B: thread tid owns dim d = tid for all 4 heads.
        const float c0 = SM_SC[0], c1 = SM_SC[1], c2 = SM_SC[2], c3 = SM_SC[3];
        acc0 *= c0; acc1 *= c1; acc2 *= c2; acc3 *= c3;

        const float4* p4s = (const float4*)SM_P;
        const float*  Vb  = SM_V(buf) + tid;
        #pragma unroll 8
        for (int j = 0; j < nt; ++j) {
            const float4 p4 = p4s[j];
            const float  v  = Vb[j * DD];
            acc0 += p4.x * v; acc1 += p4.y * v;
            acc2 += p4.z * v; acc3 += p4.w * v;
        }
        // No trailing barrier: next iteration's post-wait __syncthreads covers
        // s_s/p_s WAR; K/V buffers are double-buffered.
    }

    if (lane == 0) { SM_MF[wid] = m_run; SM_LF[wid] = l_run; }
    __syncthreads();

    const float l0 = fmaxf(SM_LF[0], 1e-30f);
    const float l1 = fmaxf(SM_LF[1], 1e-30f);
    const float l2 = fmaxf(SM_LF[2], 1e-30f);
    const float l3 = fmaxf(SM_LF[3], 1e-30f);
    g_po[(pbase + 0) * DD + tid] = acc0 / l0;
    g_po[(pbase + 1) * DD + tid] = acc1 / l1;
    g_po[(pbase + 2) * DD + tid] = acc2 / l2;
    g_po[(pbase + 3) * DD + tid] = acc3 / l3;
    if (tid < GG)
        g_plse[pbase + tid] = SM_MF[tid] + __logf(fmaxf(SM_LF[tid], 1e-30f));
}

#define CTHREADS 512
#define NSLICE 4
#define PER_SLICE (RS / NSLICE)   // 32

__global__ void __launch_bounds__(CTHREADS)
combine_kernel(float* __restrict__ out)
{
    const int bh  = blockIdx.x;     // b*HQ + hq
    const int tid = threadIdx.x;
    const int d   = tid & 127;      // output dim
    const int sl  = tid >> 7;       // slice 0..3

    __shared__ float lse_s[RS];
    __shared__ float accs[NSLICE][DD];
    __shared__ float wss[NSLICE];

    if (tid < RS)
        lse_s[tid] = g_plse[tid * (BB * HQ) + bh];
    __syncthreads();

    float gm = NEGINF;
    #pragma unroll
    for (int i = 0; i < RS; ++i)
        gm = fmaxf(gm, lse_s[i]);

    float acc = 0.f, ws = 0.f;
    #pragma unroll
    for (int t = 0; t < PER_SLICE; ++t) {
        const int   i   = sl * PER_SLICE + t;
        const float lse = lse_s[i];
        if (lse > -5.0e29f) {
            const float w = __expf(lse - gm);
            ws  += w;
            acc += w * __ldg(&g_po[(i * (BB * HQ) + bh) * DD + d]);
        }
    }
    accs[sl][d] = acc;
    if (d == 0) wss[sl] = ws;
    __syncthreads();

    if (sl == 0) {
        const float a  = accs[0][d] + accs[1][d] + accs[2][d] + accs[3][d];
        const float wt = wss[0] + wss[1] + wss[2] + wss[3];
        out[bh * DD + d] = a / fmaxf(wt, 1e-30f);
    }
}

extern "C" void kernel_launch(void* const* d_in, const int* in_sizes, int n_in,
                              void* d_out, int out_size)
{
    (void)in_sizes; (void)n_in; (void)out_size;
    const float* q    = (const float*)d_in[0];
    const float* kc   = (const float*)d_in[1];
    const float* vc   = (const float*)d_in[2];
    const int*   lens = (const int*)d_in[3];
    const int*   bt   = (const int*)d_in[4];

    cudaFuncSetAttribute(decode_kernel,
                         cudaFuncAttributeMaxDynamicSharedMemorySize, SMEM_BYTES);

    dim3 grid1(NSPLIT, HKV, RR * BB);
    decode_kernel<<<grid1, 128, SMEM_BYTES>>>(q, kc, vc, lens, bt);
    combine_kernel<<<BB * HQ, CTHREADS>>>((float*)d_out);
}